// round 13
// baseline (speedup 1.0000x reference)
#include <cuda_runtime.h>
#include <utility>

#define RB 20
#define RA 19
#define MUL 128
#define NC 128
#define NBATCH 1024
#define D1 9
#define DZ 25
#define ZSTRIDE 28       // padded z row stride (112B, 16B aligned)
#define ZROW (NC * ZSTRIDE)            // 3584 floats per node
#define XYSTRIDE 20      // [xd1..8][yd1..8][xd0][yd0][pad2]
#define XYNODE (NC * XYSTRIDE)         // 2560 floats per node staging

// ===================== compile-time selection rules =====================
__host__ __device__ constexpr int lof(int d) {
    return (d < 1) ? 0 : (d < 4) ? 1 : (d < 9) ? 2 : (d < 16) ? 3 : 4;
}
__host__ __device__ constexpr bool gaunt_nz(int i, int j, int d) {
    const int l1 = lof(i), m1 = i - l1 * l1 - l1;
    const int l2 = lof(j), m2 = j - l2 * l2 - l2;
    const int L  = lof(d), M  = d - L * L - L;
    if ((l1 + l2 + L) & 1) return false;
    const int lo = (l1 > l2) ? (l1 - l2) : (l2 - l1);
    if (L < lo || L > l1 + l2) return false;
    const int f1 = m1 < 0 ? -m1 : m1;
    const int f2 = m2 < 0 ? -m2 : m2;
    const int F  = M  < 0 ? -M  : M;
    const int fd = (f1 > f2) ? (f1 - f2) : (f2 - f1);
    if (!(F == f1 + f2 || F == fd)) return false;
    if (((m1 < 0) + (m2 < 0) + (M < 0)) & 1) return false;
    return true;
}

// ===================== compile-time Gaunt table =====================
namespace cgaunt {

constexpr double PI = 3.14159265358979323846;

constexpr double csqrt(double x) {
    double r = (x > 1.0) ? x : 1.0;
    for (int i = 0; i < 80; ++i) r = 0.5 * (r + x / r);
    return r;
}
constexpr double redang(double x) {
    while (x >  PI) x -= 2.0 * PI;
    while (x < -PI) x += 2.0 * PI;
    return x;
}
constexpr double ccos(double x) {
    x = redang(x);
    double x2 = x * x, t = 1.0, s = 1.0;
    for (int k = 1; k <= 22; ++k) { t *= -x2 / ((2.0 * k - 1.0) * (2.0 * k)); s += t; }
    return s;
}
constexpr double csin(double x) {
    x = redang(x);
    double x2 = x * x, t = x, s = x;
    for (int k = 1; k <= 22; ++k) { t *= -x2 / ((2.0 * k) * (2.0 * k + 1.0)); s += t; }
    return s;
}
constexpr double cfact(int k) { double f = 1.0; for (int v = 2; v <= k; ++v) f *= v; return f; }

constexpr double alegP(int l, int m, double x) {
    double pmm = 1.0;
    if (m > 0) {
        double df = 1.0;
        for (int k = 1; k < 2 * m; k += 2) df *= (double)k;
        double somx2 = csqrt(1.0 - x * x);
        double s = 1.0;
        for (int k = 0; k < m; ++k) s *= somx2;
        pmm = ((m & 1) ? -1.0 : 1.0) * df * s;
    }
    if (l == m) return pmm;
    double pmmp1 = x * (2.0 * m + 1.0) * pmm;
    if (l == m + 1) return pmmp1;
    for (int ll = m + 2; ll <= l; ++ll) {
        double p = ((2.0 * ll - 1.0) * x * pmmp1 - (ll + m - 1.0) * pmm) / (double)(ll - m);
        pmm = pmmp1; pmmp1 = p;
    }
    return pmmp1;
}

struct GTab { double g[81][DZ]; };

constexpr GTab make_gaunt() {
    GTab T{};
    double ct[RB] = {}, qw[RB] = {};
    for (int i = 0; i < RB; ++i) {
        double xv = ccos(PI * (i + 0.75) / (RB + 0.5));
        double dp = 0.0;
        for (int it = 0; it < 60; ++it) {
            double p0 = 1.0, p1 = xv;
            for (int k = 2; k <= RB; ++k) {
                double p = ((2.0 * k - 1.0) * xv * p1 - (k - 1.0) * p0) / (double)k;
                p0 = p1; p1 = p;
            }
            dp = RB * (xv * p1 - p0) / (xv * xv - 1.0);
            xv -= p1 / dp;
        }
        {
            double p0 = 1.0, p1 = xv;
            for (int k = 2; k <= RB; ++k) {
                double p = ((2.0 * k - 1.0) * xv * p1 - (k - 1.0) * p0) / (double)k;
                p0 = p1; p1 = p;
            }
            dp = RB * (xv * p1 - p0) / (xv * xv - 1.0);
        }
        ct[i] = xv;
        qw[i] = 2.0 / ((1.0 - xv * xv) * dp * dp);
    }
    double Pn[DZ][RB] = {}, U[DZ][RA] = {};
    for (int d = 0; d < DZ; ++d) {
        int l = lof(d);
        int m = d - l * l - l;
        int am = m < 0 ? -m : m;
        double nlm = csqrt((2.0 * l + 1.0) / (4.0 * PI) * cfact(l - am) / cfact(l + am));
        for (int b = 0; b < RB; ++b) Pn[d][b] = nlm * alegP(l, am, ct[b]);
        for (int a = 0; a < RA; ++a) {
            double al = 2.0 * PI * (double)a / (double)RA;
            U[d][a] = (m == 0) ? 1.0
                    : (m > 0 ? csqrt(2.0) * ccos((double)m * al)
                             : csqrt(2.0) * csin((double)am * al));
        }
    }
    const double scale = (2.0 * PI / (double)RA) / (double)MUL / csqrt((double)NC);
    for (int i = 0; i < 9; ++i)
        for (int j = 0; j < 9; ++j)
            for (int d = 0; d < DZ; ++d) {
                if (!gaunt_nz(i, j, d)) { T.g[i * 9 + j][d] = 0.0; continue; }
                double angs = 0.0;
                for (int a = 0; a < RA; ++a) angs += U[i][a] * U[j][a] * U[d][a];
                double bets = 0.0;
                for (int b = 0; b < RB; ++b) bets += qw[b] * Pn[i][b] * Pn[j][b] * Pn[d][b];
                T.g[i * 9 + j][d] = angs * bets * scale;
            }
    return T;
}

constexpr GTab GG = make_gaunt();

} // namespace cgaunt

// ===================== static_for =====================
template <typename F, int... Is>
__device__ __forceinline__ void sfor_impl(F&& f, std::integer_sequence<int, Is...>) {
    (f(std::integral_constant<int, Is>{}), ...);
}
template <int N, typename F>
__device__ __forceinline__ void sfor(F&& f) {
    sfor_impl(static_cast<F&&>(f), std::make_integer_sequence<int, N>{});
}

// ===================== packed f32x2 helpers =====================
__device__ __forceinline__ unsigned long long pk2(float lo, float hi) {
    unsigned long long r;
    asm("mov.b64 %0, {%1, %2};" : "=l"(r) : "f"(lo), "f"(hi));
    return r;
}
__device__ __forceinline__ void ffma2(unsigned long long& d,
                                      unsigned long long a, unsigned long long b) {
    asm("fma.rn.f32x2 %0, %1, %2, %0;" : "+l"(d) : "l"(a), "l"(b));
}
__device__ __forceinline__ void unpk2(unsigned long long v, float& lo, float& hi) {
    asm("mov.b64 {%0, %1}, %2;" : "=f"(lo), "=f"(hi) : "l"(v));
}

// ===================== device scratch =====================
__device__ float4 WX4[MUL * NC];   // (wx_l0, wx_l1, wx_l2, 0)   at [m*128+c]
__device__ float4 WY4[MUL * NC];   // (wy_l0, wy_l1, wy_l2, 0)
__device__ float4 WZ4[NC * NC];    // (wz_l0..wz_l3)             at [cc*128+c]
__device__ float2 WZ2[NC * NC];    // (wz_l3, wz_l4)
__device__ float  ZS[NBATCH * ZROW];   // 14.7 MB z scratch (padded rows)

__global__ void pack_weights(const float* __restrict__ wx,
                             const float* __restrict__ wy,
                             const float* __restrict__ wz) {
    int idx = blockIdx.x * 256 + threadIdx.x;   // 0..16383
    WX4[idx] = make_float4(wx[idx], wx[16384 + idx], wx[32768 + idx], 0.0f);
    WY4[idx] = make_float4(wy[idx], wy[16384 + idx], wy[32768 + idx], 0.0f);
    WZ4[idx] = make_float4(wz[idx], wz[16384 + idx], wz[32768 + idx], wz[49152 + idx]);
    WZ2[idx] = make_float2(wz[49152 + idx], wz[65536 + idx]);
}

// ===================== sparse Gaunt contraction (compile-time coeffs) ========
__device__ __forceinline__ void gaunt_contract_ct(const float* __restrict__ xc,
                                                  const float* __restrict__ yc,
                                                  float* __restrict__ z) {
    #pragma unroll
    for (int d = 0; d < DZ; ++d) z[d] = 0.0f;
    sfor<9>([&](auto I) {
        constexpr int i = decltype(I)::value;
        sfor<9>([&](auto J) {
            constexpr int j = decltype(J)::value;
            float p = xc[i] * yc[j];
            sfor<DZ>([&](auto Dd) {
                constexpr int d = decltype(Dd)::value;
                if constexpr (gaunt_nz(i, j, d)) {
                    constexpr float gv = (float)cgaunt::GG.g[i * 9 + j][d];
                    z[d] = fmaf(p, gv, z[d]);
                }
            });
        });
    });
}

// ===================== K1: linear-in + Gaunt, TILE_N=2, x/y-split ============
// 256 threads: c = tid&127, h = tid>>7. h=0 -> x side, h=1 -> y side.
// Each thread accumulates ITS side for BOTH nodes; one float4 weight LDG per m
// serves 2 nodes. xc/yc exchanged via smem; Gaunt phase: h = node index.
__global__ void __launch_bounds__(256, 4)
k1_linear_gaunt(const float* __restrict__ x, const float* __restrict__ y) {
    __shared__ __align__(16) float pool[2 * ZROW];      // 28672 B: xy staging, then z
    __shared__ float exch[2 * 2 * 9 * NC];              // 18432 B: [nn][side][k][c]

    const int tid = threadIdx.x;
    const int c = tid & 127;
    const int h = tid >> 7;
    const int n0 = blockIdx.x * 2;

    // ---- stage-in both nodes: per node base nn*XYNODE, row m at [m*20] ----
    {
        const float* xg = x + (size_t)n0 * MUL * D1;
        const float* yg = y + (size_t)n0 * MUL * D1;
        #pragma unroll
        for (int it = 0; it < 9; ++it) {                 // 2*1152 / 256 = 9
            int idx = tid + it * 256;
            int nn = idx / (MUL * D1);
            int r  = idx - nn * (MUL * D1);
            int m = r / 9, dd = r - m * 9;
            int kx = (dd == 0) ? 16 : (dd - 1);
            int ky = (dd == 0) ? 17 : (7 + dd);
            const float* sg = nn ? (xg + MUL * D1) : xg;
            const float* tg = nn ? (yg + MUL * D1) : yg;
            pool[nn * XYNODE + m * XYSTRIDE + kx] = sg[r];
            pool[nn * XYNODE + m * XYSTRIDE + ky] = tg[r];
        }
    }
    __syncthreads();

    // ---- stage 1: this thread's side (x or y) for both nodes ----
    const float4* wptr = h ? WY4 : WX4;                 // uniform per warp
    const int rofs = h ? 8 : 0;                          // y values at row+8
    unsigned long long A0[4], A1[4];
    float s0 = 0.0f, s1 = 0.0f;
    #pragma unroll
    for (int k = 0; k < 4; ++k) { A0[k] = A1[k] = 0ULL; }

    #pragma unroll 4
    for (int m = 0; m < MUL; ++m) {
        float4 w = wptr[m * NC + c];                     // (w0, w1, w2, -)
        unsigned long long p11 = pk2(w.y, w.y);
        unsigned long long p12 = pk2(w.y, w.z);
        unsigned long long p22 = pk2(w.z, w.z);
        {
            const float* row = &pool[m * XYSTRIDE + rofs];
            float4 v0 = *(const float4*)(row);           // d1..d4
            float4 v1 = *(const float4*)(row + 4);       // d5..d8
            float  d0 = pool[m * XYSTRIDE + 16 + h];     // xd0 or yd0
            ffma2(A0[0], pk2(v0.x, v0.y), p11);
            ffma2(A0[1], pk2(v0.z, v0.w), p12);
            ffma2(A0[2], pk2(v1.x, v1.y), p22);
            ffma2(A0[3], pk2(v1.z, v1.w), p22);
            s0 += d0 * w.x;
        }
        {
            const float* row = &pool[XYNODE + m * XYSTRIDE + rofs];
            float4 v0 = *(const float4*)(row);
            float4 v1 = *(const float4*)(row + 4);
            float  d0 = pool[XYNODE + m * XYSTRIDE + 16 + h];
            ffma2(A1[0], pk2(v0.x, v0.y), p11);
            ffma2(A1[1], pk2(v0.z, v0.w), p12);
            ffma2(A1[2], pk2(v1.x, v1.y), p22);
            ffma2(A1[3], pk2(v1.z, v1.w), p22);
            s1 += d0 * w.x;
        }
    }

    // ---- write this side's coefficients to exchange: [nn][h][k][c] ----
    {
        float v[9];
        v[0] = s0;
        #pragma unroll
        for (int k = 0; k < 4; ++k) unpk2(A0[k], v[2 * k + 1], v[2 * k + 2]);
        #pragma unroll
        for (int k = 0; k < 9; ++k) exch[((0 * 2 + h) * 9 + k) * NC + c] = v[k];
        v[0] = s1;
        #pragma unroll
        for (int k = 0; k < 4; ++k) unpk2(A1[k], v[2 * k + 1], v[2 * k + 2]);
        #pragma unroll
        for (int k = 0; k < 9; ++k) exch[((1 * 2 + h) * 9 + k) * NC + c] = v[k];
    }
    __syncthreads();

    // ---- Gaunt: thread (c,h) handles node h entirely; z -> pool (xy dead) ----
    {
        float xc[9], yc[9];
        #pragma unroll
        for (int k = 0; k < 9; ++k) {
            xc[k] = exch[((h * 2 + 0) * 9 + k) * NC + c];
            yc[k] = exch[((h * 2 + 1) * 9 + k) * NC + c];
        }
        float z[DZ];
        gaunt_contract_ct(xc, yc, z);
        float* zr = &pool[h * ZROW + c * ZSTRIDE];       // 16B aligned
        *(float4*)(zr)      = make_float4(z[0],  z[1],  z[2],  z[3]);
        *(float4*)(zr + 4)  = make_float4(z[4],  z[5],  z[6],  z[7]);
        *(float4*)(zr + 8)  = make_float4(z[8],  z[9],  z[10], z[11]);
        *(float4*)(zr + 12) = make_float4(z[12], z[13], z[14], z[15]);
        *(float4*)(zr + 16) = make_float4(z[16], z[17], z[18], z[19]);
        *(float4*)(zr + 20) = make_float4(z[20], z[21], z[22], z[23]);
        zr[24] = z[24];
    }
    __syncthreads();

    // ---- coalesced copy: both nodes contiguous in ZS ----
    float4* zg4 = (float4*)(ZS + (size_t)n0 * ZROW);
    const float4* p4 = (const float4*)pool;
    #pragma unroll
    for (int it = 0; it < 7; ++it) {                     // 2*896 / 256 = 7
        zg4[it * 256 + tid] = p4[it * 256 + tid];
    }
}

// ===================== K2: channel mixing, TILE_N=2, d-split =================
// 256 threads: c = tid&127, h = tid>>7.
// h=0 owns outputs d0..12 (WZ4); h=1 owns d13..24 (WZ2). Each thread handles
// BOTH nodes: one weight LDG per cc serves 2 nodes. z reads are broadcast.
__global__ void __launch_bounds__(256, 4)
k2_mix(float* __restrict__ out) {
    __shared__ __align__(16) float zs[2 * ZROW];   // 28672 B

    const int tid = threadIdx.x;
    const int c = tid & 127;
    const int h = tid >> 7;
    const int n0 = blockIdx.x * 2;

    // ---- stage z in: straight float4 copy for both nodes ----
    {
        const float4* zg4 = (const float4*)(ZS + (size_t)n0 * ZROW);
        float4* s4 = (float4*)zs;
        #pragma unroll
        for (int it = 0; it < 7; ++it) {
            s4[it * 256 + tid] = zg4[it * 256 + tid];
        }
    }
    __syncthreads();

    unsigned long long a0[6], a1[6];
    float at0 = 0.0f, at1 = 0.0f;
    #pragma unroll
    for (int k = 0; k < 6; ++k) { a0[k] = a1[k] = 0ULL; }

    if (h == 0) {
        #pragma unroll 4
        for (int cc = 0; cc < NC; ++cc) {
            float4 wv = WZ4[cc * NC + c];
            unsigned long long p01 = pk2(wv.x, wv.y);
            unsigned long long p11 = pk2(wv.y, wv.y);
            unsigned long long p22 = pk2(wv.z, wv.z);
            unsigned long long p23 = pk2(wv.z, wv.w);
            unsigned long long p33 = pk2(wv.w, wv.w);
            {
                const float* zp = &zs[cc * ZSTRIDE];
                float4 q0 = *(const float4*)(zp);
                float4 q1 = *(const float4*)(zp + 4);
                float4 q2 = *(const float4*)(zp + 8);
                ffma2(a0[0], pk2(q0.x, q0.y), p01);
                ffma2(a0[1], pk2(q0.z, q0.w), p11);
                ffma2(a0[2], pk2(q1.x, q1.y), p22);
                ffma2(a0[3], pk2(q1.z, q1.w), p22);
                ffma2(a0[4], pk2(q2.x, q2.y), p23);
                ffma2(a0[5], pk2(q2.z, q2.w), p33);
                at0 += zp[12] * wv.w;
            }
            {
                const float* zp = &zs[ZROW + cc * ZSTRIDE];
                float4 q0 = *(const float4*)(zp);
                float4 q1 = *(const float4*)(zp + 4);
                float4 q2 = *(const float4*)(zp + 8);
                ffma2(a1[0], pk2(q0.x, q0.y), p01);
                ffma2(a1[1], pk2(q0.z, q0.w), p11);
                ffma2(a1[2], pk2(q1.x, q1.y), p22);
                ffma2(a1[3], pk2(q1.z, q1.w), p22);
                ffma2(a1[4], pk2(q2.x, q2.y), p23);
                ffma2(a1[5], pk2(q2.z, q2.w), p33);
                at1 += zp[12] * wv.w;
            }
        }
    } else {
        #pragma unroll 4
        for (int cc = 0; cc < NC; ++cc) {
            float2 wv = WZ2[cc * NC + c];
            unsigned long long p33 = pk2(wv.x, wv.x);
            unsigned long long p34 = pk2(wv.x, wv.y);
            unsigned long long p44 = pk2(wv.y, wv.y);
            {
                const float* zp = &zs[cc * ZSTRIDE];
                float  z13 = zp[13];
                float2 z14 = *(const float2*)(zp + 14);
                float4 q4  = *(const float4*)(zp + 16);
                float4 q5  = *(const float4*)(zp + 20);
                ffma2(a0[0], pk2(z13, z14.x), p33);
                ffma2(a0[1], pk2(z14.y, q4.x), p34);
                ffma2(a0[2], pk2(q4.y, q4.z), p44);
                ffma2(a0[3], pk2(q4.w, q5.x), p44);
                ffma2(a0[4], pk2(q5.y, q5.z), p44);
                ffma2(a0[5], pk2(q5.w, zp[24]), p44);
            }
            {
                const float* zp = &zs[ZROW + cc * ZSTRIDE];
                float  z13 = zp[13];
                float2 z14 = *(const float2*)(zp + 14);
                float4 q4  = *(const float4*)(zp + 16);
                float4 q5  = *(const float4*)(zp + 20);
                ffma2(a1[0], pk2(z13, z14.x), p33);
                ffma2(a1[1], pk2(z14.y, q4.x), p34);
                ffma2(a1[2], pk2(q4.y, q4.z), p44);
                ffma2(a1[3], pk2(q4.w, q5.x), p44);
                ffma2(a1[4], pk2(q5.y, q5.z), p44);
                ffma2(a1[5], pk2(q5.w, zp[24]), p44);
            }
        }
    }
    __syncthreads();   // all reads of zs done before epilogue overwrite

    // ---- epilogue: out-layout in smem [nn*3200 + c*25 + d], then copy ----
    {
        float lo, hi;
        if (h == 0) {
            float* r0 = &zs[c * DZ];
            #pragma unroll
            for (int k = 0; k < 6; ++k) {
                unpk2(a0[k], lo, hi);
                r0[2 * k] = lo; r0[2 * k + 1] = hi;
            }
            r0[12] = at0;
            float* r1 = &zs[NC * DZ + c * DZ];
            #pragma unroll
            for (int k = 0; k < 6; ++k) {
                unpk2(a1[k], lo, hi);
                r1[2 * k] = lo; r1[2 * k + 1] = hi;
            }
            r1[12] = at1;
        } else {
            float* r0 = &zs[c * DZ];
            #pragma unroll
            for (int k = 0; k < 6; ++k) {
                unpk2(a0[k], lo, hi);
                r0[13 + 2 * k] = lo;
                if (13 + 2 * k + 1 < DZ) r0[13 + 2 * k + 1] = hi;
            }
            float* r1 = &zs[NC * DZ + c * DZ];
            #pragma unroll
            for (int k = 0; k < 6; ++k) {
                unpk2(a1[k], lo, hi);
                r1[13 + 2 * k] = lo;
                if (13 + 2 * k + 1 < DZ) r1[13 + 2 * k + 1] = hi;
            }
        }
    }
    __syncthreads();

    // ---- fully coalesced copy: 2 nodes = 6400 floats = 1600 float4 ----
    float* og = out + (size_t)n0 * (NC * DZ);
    float4* og4 = (float4*)og;
    const float4* s4 = (const float4*)zs;
    #pragma unroll
    for (int it = 0; it < 7; ++it) {
        int i = tid + it * 256;
        if (i < (2 * NC * DZ) / 4) og4[i] = s4[i];
    }
}

extern "C" void kernel_launch(void* const* d_in, const int* in_sizes, int n_in,
                              void* d_out, int out_size) {
    const float* x  = (const float*)d_in[0];
    const float* y  = (const float*)d_in[1];
    const float* wx = (const float*)d_in[2];
    const float* wy = (const float*)d_in[3];
    const float* wz = (const float*)d_in[4];
    float* out = (float*)d_out;

    pack_weights<<<64, 256>>>(wx, wy, wz);
    k1_linear_gaunt<<<NBATCH / 2, 256>>>(x, y);
    k2_mix<<<NBATCH / 2, 256>>>(out);
}

// round 16
// speedup vs baseline: 1.1940x; 1.1940x over previous
#include <cuda_runtime.h>
#include <cuda_fp16.h>
#include <utility>

#define RB 20
#define RA 19
#define MUL 128
#define NC 128
#define NBATCH 1024
#define D1 9
#define DZ 25
#define ZSTRIDE 28     // padded z row stride (112B, 16B aligned)
#define ZROW (NC * ZSTRIDE)          // 3584 floats per node in scratch
#define XYSTRIDE 20    // [xd1..8][yd1..8][xd0][yd0][pad2] (80B, 16B aligned)

// ===================== compile-time selection rules =====================
__host__ __device__ constexpr int lof(int d) {
    return (d < 1) ? 0 : (d < 4) ? 1 : (d < 9) ? 2 : (d < 16) ? 3 : 4;
}
__host__ __device__ constexpr bool gaunt_nz(int i, int j, int d) {
    const int l1 = lof(i), m1 = i - l1 * l1 - l1;
    const int l2 = lof(j), m2 = j - l2 * l2 - l2;
    const int L  = lof(d), M  = d - L * L - L;
    if ((l1 + l2 + L) & 1) return false;
    const int lo = (l1 > l2) ? (l1 - l2) : (l2 - l1);
    if (L < lo || L > l1 + l2) return false;
    const int f1 = m1 < 0 ? -m1 : m1;
    const int f2 = m2 < 0 ? -m2 : m2;
    const int F  = M  < 0 ? -M  : M;
    const int fd = (f1 > f2) ? (f1 - f2) : (f2 - f1);
    if (!(F == f1 + f2 || F == fd)) return false;
    if (((m1 < 0) + (m2 < 0) + (M < 0)) & 1) return false;
    return true;
}

// ===================== compile-time Gaunt table =====================
namespace cgaunt {

constexpr double PI = 3.14159265358979323846;

constexpr double csqrt(double x) {
    double r = (x > 1.0) ? x : 1.0;
    for (int i = 0; i < 80; ++i) r = 0.5 * (r + x / r);
    return r;
}
constexpr double redang(double x) {
    while (x >  PI) x -= 2.0 * PI;
    while (x < -PI) x += 2.0 * PI;
    return x;
}
constexpr double ccos(double x) {
    x = redang(x);
    double x2 = x * x, t = 1.0, s = 1.0;
    for (int k = 1; k <= 22; ++k) { t *= -x2 / ((2.0 * k - 1.0) * (2.0 * k)); s += t; }
    return s;
}
constexpr double csin(double x) {
    x = redang(x);
    double x2 = x * x, t = x, s = x;
    for (int k = 1; k <= 22; ++k) { t *= -x2 / ((2.0 * k) * (2.0 * k + 1.0)); s += t; }
    return s;
}
constexpr double cfact(int k) { double f = 1.0; for (int v = 2; v <= k; ++v) f *= v; return f; }

constexpr double alegP(int l, int m, double x) {
    double pmm = 1.0;
    if (m > 0) {
        double df = 1.0;
        for (int k = 1; k < 2 * m; k += 2) df *= (double)k;
        double somx2 = csqrt(1.0 - x * x);
        double s = 1.0;
        for (int k = 0; k < m; ++k) s *= somx2;
        pmm = ((m & 1) ? -1.0 : 1.0) * df * s;
    }
    if (l == m) return pmm;
    double pmmp1 = x * (2.0 * m + 1.0) * pmm;
    if (l == m + 1) return pmmp1;
    for (int ll = m + 2; ll <= l; ++ll) {
        double p = ((2.0 * ll - 1.0) * x * pmmp1 - (ll + m - 1.0) * pmm) / (double)(ll - m);
        pmm = pmmp1; pmmp1 = p;
    }
    return pmmp1;
}

struct GTab { double g[81][DZ]; };

constexpr GTab make_gaunt() {
    GTab T{};
    double ct[RB] = {}, qw[RB] = {};
    for (int i = 0; i < RB; ++i) {
        double xv = ccos(PI * (i + 0.75) / (RB + 0.5));
        double dp = 0.0;
        for (int it = 0; it < 60; ++it) {
            double p0 = 1.0, p1 = xv;
            for (int k = 2; k <= RB; ++k) {
                double p = ((2.0 * k - 1.0) * xv * p1 - (k - 1.0) * p0) / (double)k;
                p0 = p1; p1 = p;
            }
            dp = RB * (xv * p1 - p0) / (xv * xv - 1.0);
            xv -= p1 / dp;
        }
        {
            double p0 = 1.0, p1 = xv;
            for (int k = 2; k <= RB; ++k) {
                double p = ((2.0 * k - 1.0) * xv * p1 - (k - 1.0) * p0) / (double)k;
                p0 = p1; p1 = p;
            }
            dp = RB * (xv * p1 - p0) / (xv * xv - 1.0);
        }
        ct[i] = xv;
        qw[i] = 2.0 / ((1.0 - xv * xv) * dp * dp);
    }
    double Pn[DZ][RB] = {}, U[DZ][RA] = {};
    for (int d = 0; d < DZ; ++d) {
        int l = lof(d);
        int m = d - l * l - l;
        int am = m < 0 ? -m : m;
        double nlm = csqrt((2.0 * l + 1.0) / (4.0 * PI) * cfact(l - am) / cfact(l + am));
        for (int b = 0; b < RB; ++b) Pn[d][b] = nlm * alegP(l, am, ct[b]);
        for (int a = 0; a < RA; ++a) {
            double al = 2.0 * PI * (double)a / (double)RA;
            U[d][a] = (m == 0) ? 1.0
                    : (m > 0 ? csqrt(2.0) * ccos((double)m * al)
                             : csqrt(2.0) * csin((double)am * al));
        }
    }
    const double scale = (2.0 * PI / (double)RA) / (double)MUL / csqrt((double)NC);
    for (int i = 0; i < 9; ++i)
        for (int j = 0; j < 9; ++j)
            for (int d = 0; d < DZ; ++d) {
                if (!gaunt_nz(i, j, d)) { T.g[i * 9 + j][d] = 0.0; continue; }
                double angs = 0.0;
                for (int a = 0; a < RA; ++a) angs += U[i][a] * U[j][a] * U[d][a];
                double bets = 0.0;
                for (int b = 0; b < RB; ++b) bets += qw[b] * Pn[i][b] * Pn[j][b] * Pn[d][b];
                T.g[i * 9 + j][d] = angs * bets * scale;
            }
    return T;
}

constexpr GTab GG = make_gaunt();

} // namespace cgaunt

// ===================== static_for =====================
template <typename F, int... Is>
__device__ __forceinline__ void sfor_impl(F&& f, std::integer_sequence<int, Is...>) {
    (f(std::integral_constant<int, Is>{}), ...);
}
template <int N, typename F>
__device__ __forceinline__ void sfor(F&& f) {
    sfor_impl(static_cast<F&&>(f), std::make_integer_sequence<int, N>{});
}

// ===================== packed f32x2 helpers =====================
__device__ __forceinline__ unsigned long long pk2(float lo, float hi) {
    unsigned long long r;
    asm("mov.b64 %0, {%1, %2};" : "=l"(r) : "f"(lo), "f"(hi));
    return r;
}
__device__ __forceinline__ void ffma2(unsigned long long& d,
                                      unsigned long long a, unsigned long long b) {
    asm("fma.rn.f32x2 %0, %1, %2, %0;" : "+l"(d) : "l"(a), "l"(b));
}
__device__ __forceinline__ void unpk2(unsigned long long v, float& lo, float& hi) {
    asm("mov.b64 {%0, %1}, %2;" : "=f"(lo), "=f"(hi) : "l"(v));
}

// ===================== half2 <-> uint bit casts =====================
__device__ __forceinline__ unsigned h2u(__half2 h) {
    return *reinterpret_cast<unsigned*>(&h);
}
__device__ __forceinline__ __half2 u2h(unsigned u) {
    return *reinterpret_cast<__half2*>(&u);
}

// ===================== device scratch: fp16-packed weights =====================
// K1: per (m,c): WH1 = (wx_l0,wx_l1 | wx_l2,wy_l0) 8B; WH2 = (wy_l1,wy_l2) 4B
// K2: per (cc,c): WZH1 = (w0,w1 | w2,w3) 8B; WZH2 = (w4,w4) 4B
__device__ uint2     WH1[MUL * NC];
__device__ unsigned  WH2[MUL * NC];
__device__ uint2     WZH1[NC * NC];
__device__ unsigned  WZH2[NC * NC];
__device__ float     ZS[NBATCH * ZROW];   // 14.7 MB z scratch (padded rows)

__global__ void pack_weights(const float* __restrict__ wx,
                             const float* __restrict__ wy,
                             const float* __restrict__ wz) {
    int idx = blockIdx.x * 256 + threadIdx.x;   // 0..16383
    {
        __half2 a = __floats2half2_rn(wx[idx], wx[16384 + idx]);          // wx0, wx1
        __half2 b = __floats2half2_rn(wx[32768 + idx], wy[idx]);          // wx2, wy0
        __half2 c = __floats2half2_rn(wy[16384 + idx], wy[32768 + idx]);  // wy1, wy2
        WH1[idx] = make_uint2(h2u(a), h2u(b));
        WH2[idx] = h2u(c);
    }
    {
        __half2 a = __floats2half2_rn(wz[idx], wz[16384 + idx]);          // w0, w1
        __half2 b = __floats2half2_rn(wz[32768 + idx], wz[49152 + idx]);  // w2, w3
        __half2 c = __floats2half2_rn(wz[65536 + idx], wz[65536 + idx]);  // w4, w4
        WZH1[idx] = make_uint2(h2u(a), h2u(b));
        WZH2[idx] = h2u(c);
    }
}

// ===================== sparse Gaunt contraction (compile-time coeffs) ========
__device__ __forceinline__ void gaunt_contract_ct(const float* __restrict__ xc,
                                                  const float* __restrict__ yc,
                                                  float* __restrict__ z) {
    #pragma unroll
    for (int d = 0; d < DZ; ++d) z[d] = 0.0f;
    sfor<9>([&](auto I) {
        constexpr int i = decltype(I)::value;
        sfor<9>([&](auto J) {
            constexpr int j = decltype(J)::value;
            float p = xc[i] * yc[j];
            sfor<DZ>([&](auto Dd) {
                constexpr int d = decltype(Dd)::value;
                if constexpr (gaunt_nz(i, j, d)) {
                    constexpr float gv = (float)cgaunt::GG.g[i * 9 + j][d];
                    z[d] = fmaf(p, gv, z[d]);
                }
            });
        });
    });
}

// ===================== K1: linear-in + Gaunt -> z scratch (R9 + fp16 wts) ====
__global__ void __launch_bounds__(128, 9)
k1_linear_gaunt(const float* __restrict__ x, const float* __restrict__ y) {
    __shared__ __align__(16) float pool[ZROW];   // 14336 B

    const int c = threadIdx.x;
    const int n = blockIdx.x;

    // ---- stage-in: xy row m = [xd1..8][yd1..8][xd0][yd0][pad2] ----
    {
        const float* xg = x + (size_t)n * MUL * D1;
        const float* yg = y + (size_t)n * MUL * D1;
        #pragma unroll
        for (int it = 0; it < 9; ++it) {
            int idx = c + it * 128;
            int m = idx / 9, dd = idx - m * 9;
            int kx = (dd == 0) ? 16 : (dd - 1);
            int ky = (dd == 0) ? 17 : (7 + dd);
            pool[m * XYSTRIDE + kx] = xg[idx];
            pool[m * XYSTRIDE + ky] = yg[idx];
        }
    }
    __syncthreads();

    // ---- stage 1: per-l linear in (packed f32x2, fp16 weights) ----
    unsigned long long Ax[4], Ay[4];
    float sx = 0.0f, sy = 0.0f;
    #pragma unroll
    for (int k = 0; k < 4; ++k) { Ax[k] = Ay[k] = 0ULL; }

    #pragma unroll 4
    for (int m = 0; m < MUL; ++m) {
        uint2 w1 = WH1[m * NC + c];
        unsigned w2 = WH2[m * NC + c];
        float2 t0 = __half22float2(u2h(w1.x));   // wx0, wx1
        float2 t1 = __half22float2(u2h(w1.y));   // wx2, wy0
        float2 t2 = __half22float2(u2h(w2));     // wy1, wy2
        const float* row = &pool[m * XYSTRIDE];
        float4 xv0 = *(const float4*)(row);       // xd1..xd4
        float4 xv1 = *(const float4*)(row + 4);   // xd5..xd8
        float4 yv0 = *(const float4*)(row + 8);   // yd1..yd4
        float4 yv1 = *(const float4*)(row + 12);  // yd5..yd8
        float2 d0  = *(const float2*)(row + 16);  // xd0, yd0
        ffma2(Ax[0], pk2(xv0.x, xv0.y), pk2(t0.y, t0.y));
        ffma2(Ax[1], pk2(xv0.z, xv0.w), pk2(t0.y, t1.x));
        ffma2(Ax[2], pk2(xv1.x, xv1.y), pk2(t1.x, t1.x));
        ffma2(Ax[3], pk2(xv1.z, xv1.w), pk2(t1.x, t1.x));
        sx += d0.x * t0.x;
        ffma2(Ay[0], pk2(yv0.x, yv0.y), pk2(t2.x, t2.x));
        ffma2(Ay[1], pk2(yv0.z, yv0.w), pk2(t2.x, t2.y));
        ffma2(Ay[2], pk2(yv1.x, yv1.y), pk2(t2.y, t2.y));
        ffma2(Ay[3], pk2(yv1.z, yv1.w), pk2(t2.y, t2.y));
        sy += d0.y * t1.y;
    }

    float xc[9], yc[9];
    xc[0] = sx; yc[0] = sy;
    #pragma unroll
    for (int k = 0; k < 4; ++k) {
        unpk2(Ax[k], xc[2 * k + 1], xc[2 * k + 2]);
        unpk2(Ay[k], yc[2 * k + 1], yc[2 * k + 2]);
    }

    // ---- stage 2: sparse Gaunt contraction (registers + immediates only) ----
    float z[DZ];
    gaunt_contract_ct(xc, yc, z);

    __syncthreads();   // all warps done reading xy before z overwrites pool

    // ---- z -> smem padded rows, then coalesced float4 copy to scratch ----
    {
        float* zr = &pool[c * ZSTRIDE];  // 112B stride -> 16B aligned
        *(float4*)(zr)      = make_float4(z[0],  z[1],  z[2],  z[3]);
        *(float4*)(zr + 4)  = make_float4(z[4],  z[5],  z[6],  z[7]);
        *(float4*)(zr + 8)  = make_float4(z[8],  z[9],  z[10], z[11]);
        *(float4*)(zr + 12) = make_float4(z[12], z[13], z[14], z[15]);
        *(float4*)(zr + 16) = make_float4(z[16], z[17], z[18], z[19]);
        *(float4*)(zr + 20) = make_float4(z[20], z[21], z[22], z[23]);
        zr[24] = z[24];
    }
    __syncthreads();

    float4* zg4 = (float4*)(ZS + (size_t)n * ZROW);     // n*14336B, 16B aligned
    const float4* p4 = (const float4*)pool;
    #pragma unroll
    for (int it = 0; it < 7; ++it) {                     // 7*128 = 896 = ZROW/4
        zg4[it * 128 + c] = p4[it * 128 + c];
    }
}

// ===================== K2: channel mixing (R9 + fp16 wts) =====================
// d -> l map: d0:w0, d1-3:w1, d4-8:w2, d9-15:w3, d16-24:w4
__global__ void __launch_bounds__(128, 7)
k2_mix(float* __restrict__ out) {
    __shared__ __align__(16) float zs[ZROW];   // 14336 B

    const int c = threadIdx.x;
    const int n = blockIdx.x;

    // ---- stage z in: straight float4 copy (padded layout preserved) ----
    {
        const float4* zg4 = (const float4*)(ZS + (size_t)n * ZROW);
        float4* s4 = (float4*)zs;
        #pragma unroll
        for (int it = 0; it < 7; ++it) {
            s4[it * 128 + c] = zg4[it * 128 + c];
        }
    }
    __syncthreads();

    // ---- per-l channel mixing, packed f32x2, fp16 weights ----
    unsigned long long a[12];
    float as = 0.0f;
    #pragma unroll
    for (int k = 0; k < 12; ++k) a[k] = 0ULL;

    #pragma unroll 2
    for (int cc = 0; cc < NC; ++cc) {
        uint2 wz1 = WZH1[cc * NC + c];
        unsigned wz2 = WZH2[cc * NC + c];
        float2 t0 = __half22float2(u2h(wz1.x));  // w0, w1
        float2 t1 = __half22float2(u2h(wz1.y));  // w2, w3
        float2 t2 = __half22float2(u2h(wz2));    // w4, w4
        const float* zp = &zs[cc * ZSTRIDE];
        float4 q0 = *(const float4*)(zp);
        float4 q1 = *(const float4*)(zp + 4);
        float4 q2 = *(const float4*)(zp + 8);
        float4 q3 = *(const float4*)(zp + 12);
        float4 q4 = *(const float4*)(zp + 16);
        float4 q5 = *(const float4*)(zp + 20);
        float  zl = zp[24];
        ffma2(a[0],  pk2(q0.x, q0.y), pk2(t0.x, t0.y));   // d0*w0, d1*w1
        ffma2(a[1],  pk2(q0.z, q0.w), pk2(t0.y, t0.y));   // d2,d3 * w1
        ffma2(a[2],  pk2(q1.x, q1.y), pk2(t1.x, t1.x));   // d4,d5 * w2
        ffma2(a[3],  pk2(q1.z, q1.w), pk2(t1.x, t1.x));   // d6,d7 * w2
        ffma2(a[4],  pk2(q2.x, q2.y), pk2(t1.x, t1.y));   // d8*w2, d9*w3
        ffma2(a[5],  pk2(q2.z, q2.w), pk2(t1.y, t1.y));   // d10,d11 * w3
        ffma2(a[6],  pk2(q3.x, q3.y), pk2(t1.y, t1.y));   // d12,d13 * w3
        ffma2(a[7],  pk2(q3.z, q3.w), pk2(t1.y, t1.y));   // d14,d15 * w3  (FIXED)
        ffma2(a[8],  pk2(q4.x, q4.y), pk2(t2.x, t2.x));   // d16,d17 * w4
        ffma2(a[9],  pk2(q4.z, q4.w), pk2(t2.x, t2.x));   // d18,d19 * w4
        ffma2(a[10], pk2(q5.x, q5.y), pk2(t2.x, t2.x));   // d20,d21 * w4
        ffma2(a[11], pk2(q5.z, q5.w), pk2(t2.x, t2.x));   // d22,d23 * w4
        as += zl * t2.x;                                   // d24*w4
    }
    __syncthreads();   // everyone done reading zs before epilogue overwrites it

    // ---- epilogue: accums -> smem unpadded (stride 25: conflict-free), ----
    // ---- then fully coalesced copy to out                               ----
    {
        float* r = &zs[c * DZ];
        #pragma unroll
        for (int k = 0; k < 12; ++k) {
            float lo, hi;
            unpk2(a[k], lo, hi);
            r[2 * k] = lo;
            r[2 * k + 1] = hi;
        }
        r[24] = as;
    }
    __syncthreads();

    float* og = out + (size_t)n * (NC * DZ);            // n*12800B: 16B aligned
    float4* og4 = (float4*)og;
    const float4* s4 = (const float4*)zs;
    #pragma unroll
    for (int it = 0; it < 6; ++it) {                     // 6*128*4 = 3072 floats
        og4[it * 128 + c] = s4[it * 128 + c];
    }
    og[3072 + c] = zs[3072 + c];                         // tail 128 floats
}

extern "C" void kernel_launch(void* const* d_in, const int* in_sizes, int n_in,
                              void* d_out, int out_size) {
    const float* x  = (const float*)d_in[0];
    const float* y  = (const float*)d_in[1];
    const float* wx = (const float*)d_in[2];
    const float* wy = (const float*)d_in[3];
    const float* wz = (const float*)d_in[4];
    float* out = (float*)d_out;

    pack_weights<<<64, 256>>>(wx, wy, wz);
    k1_linear_gaunt<<<NBATCH, 128>>>(x, y);
    k2_mix<<<NBATCH, 128>>>(out);
}

// round 17
// speedup vs baseline: 1.2434x; 1.0414x over previous
#include <cuda_runtime.h>
#include <cuda_fp16.h>
#include <utility>

#define RB 20
#define RA 19
#define MUL 128
#define NC 128
#define NBATCH 1024
#define D1 9
#define DZ 25
#define ZSTRIDE 28     // padded z row stride (112B, 16B aligned)
#define ZROW (NC * ZSTRIDE)          // 3584 floats per node in scratch
#define XYSTRIDE 20    // [xd1..8][yd1..8][xd0][yd0][pad2] (80B, 16B aligned)

// ===================== compile-time selection rules =====================
__host__ __device__ constexpr int lof(int d) {
    return (d < 1) ? 0 : (d < 4) ? 1 : (d < 9) ? 2 : (d < 16) ? 3 : 4;
}
__host__ __device__ constexpr bool gaunt_nz(int i, int j, int d) {
    const int l1 = lof(i), m1 = i - l1 * l1 - l1;
    const int l2 = lof(j), m2 = j - l2 * l2 - l2;
    const int L  = lof(d), M  = d - L * L - L;
    if ((l1 + l2 + L) & 1) return false;
    const int lo = (l1 > l2) ? (l1 - l2) : (l2 - l1);
    if (L < lo || L > l1 + l2) return false;
    const int f1 = m1 < 0 ? -m1 : m1;
    const int f2 = m2 < 0 ? -m2 : m2;
    const int F  = M  < 0 ? -M  : M;
    const int fd = (f1 > f2) ? (f1 - f2) : (f2 - f1);
    if (!(F == f1 + f2 || F == fd)) return false;
    if (((m1 < 0) + (m2 < 0) + (M < 0)) & 1) return false;
    return true;
}

// ===================== compile-time Gaunt table =====================
namespace cgaunt {

constexpr double PI = 3.14159265358979323846;

constexpr double csqrt(double x) {
    double r = (x > 1.0) ? x : 1.0;
    for (int i = 0; i < 80; ++i) r = 0.5 * (r + x / r);
    return r;
}
constexpr double redang(double x) {
    while (x >  PI) x -= 2.0 * PI;
    while (x < -PI) x += 2.0 * PI;
    return x;
}
constexpr double ccos(double x) {
    x = redang(x);
    double x2 = x * x, t = 1.0, s = 1.0;
    for (int k = 1; k <= 22; ++k) { t *= -x2 / ((2.0 * k - 1.0) * (2.0 * k)); s += t; }
    return s;
}
constexpr double csin(double x) {
    x = redang(x);
    double x2 = x * x, t = x, s = x;
    for (int k = 1; k <= 22; ++k) { t *= -x2 / ((2.0 * k) * (2.0 * k + 1.0)); s += t; }
    return s;
}
constexpr double cfact(int k) { double f = 1.0; for (int v = 2; v <= k; ++v) f *= v; return f; }

constexpr double alegP(int l, int m, double x) {
    double pmm = 1.0;
    if (m > 0) {
        double df = 1.0;
        for (int k = 1; k < 2 * m; k += 2) df *= (double)k;
        double somx2 = csqrt(1.0 - x * x);
        double s = 1.0;
        for (int k = 0; k < m; ++k) s *= somx2;
        pmm = ((m & 1) ? -1.0 : 1.0) * df * s;
    }
    if (l == m) return pmm;
    double pmmp1 = x * (2.0 * m + 1.0) * pmm;
    if (l == m + 1) return pmmp1;
    for (int ll = m + 2; ll <= l; ++ll) {
        double p = ((2.0 * ll - 1.0) * x * pmmp1 - (ll + m - 1.0) * pmm) / (double)(ll - m);
        pmm = pmmp1; pmmp1 = p;
    }
    return pmmp1;
}

struct GTab { double g[81][DZ]; };

constexpr GTab make_gaunt() {
    GTab T{};
    double ct[RB] = {}, qw[RB] = {};
    for (int i = 0; i < RB; ++i) {
        double xv = ccos(PI * (i + 0.75) / (RB + 0.5));
        double dp = 0.0;
        for (int it = 0; it < 60; ++it) {
            double p0 = 1.0, p1 = xv;
            for (int k = 2; k <= RB; ++k) {
                double p = ((2.0 * k - 1.0) * xv * p1 - (k - 1.0) * p0) / (double)k;
                p0 = p1; p1 = p;
            }
            dp = RB * (xv * p1 - p0) / (xv * xv - 1.0);
            xv -= p1 / dp;
        }
        {
            double p0 = 1.0, p1 = xv;
            for (int k = 2; k <= RB; ++k) {
                double p = ((2.0 * k - 1.0) * xv * p1 - (k - 1.0) * p0) / (double)k;
                p0 = p1; p1 = p;
            }
            dp = RB * (xv * p1 - p0) / (xv * xv - 1.0);
        }
        ct[i] = xv;
        qw[i] = 2.0 / ((1.0 - xv * xv) * dp * dp);
    }
    double Pn[DZ][RB] = {}, U[DZ][RA] = {};
    for (int d = 0; d < DZ; ++d) {
        int l = lof(d);
        int m = d - l * l - l;
        int am = m < 0 ? -m : m;
        double nlm = csqrt((2.0 * l + 1.0) / (4.0 * PI) * cfact(l - am) / cfact(l + am));
        for (int b = 0; b < RB; ++b) Pn[d][b] = nlm * alegP(l, am, ct[b]);
        for (int a = 0; a < RA; ++a) {
            double al = 2.0 * PI * (double)a / (double)RA;
            U[d][a] = (m == 0) ? 1.0
                    : (m > 0 ? csqrt(2.0) * ccos((double)m * al)
                             : csqrt(2.0) * csin((double)am * al));
        }
    }
    const double scale = (2.0 * PI / (double)RA) / (double)MUL / csqrt((double)NC);
    for (int i = 0; i < 9; ++i)
        for (int j = 0; j < 9; ++j)
            for (int d = 0; d < DZ; ++d) {
                if (!gaunt_nz(i, j, d)) { T.g[i * 9 + j][d] = 0.0; continue; }
                double angs = 0.0;
                for (int a = 0; a < RA; ++a) angs += U[i][a] * U[j][a] * U[d][a];
                double bets = 0.0;
                for (int b = 0; b < RB; ++b) bets += qw[b] * Pn[i][b] * Pn[j][b] * Pn[d][b];
                T.g[i * 9 + j][d] = angs * bets * scale;
            }
    return T;
}

constexpr GTab GG = make_gaunt();

} // namespace cgaunt

// ===================== static_for =====================
template <typename F, int... Is>
__device__ __forceinline__ void sfor_impl(F&& f, std::integer_sequence<int, Is...>) {
    (f(std::integral_constant<int, Is>{}), ...);
}
template <int N, typename F>
__device__ __forceinline__ void sfor(F&& f) {
    sfor_impl(static_cast<F&&>(f), std::make_integer_sequence<int, N>{});
}

// ===================== packed f32x2 helpers =====================
__device__ __forceinline__ unsigned long long pk2(float lo, float hi) {
    unsigned long long r;
    asm("mov.b64 %0, {%1, %2};" : "=l"(r) : "f"(lo), "f"(hi));
    return r;
}
__device__ __forceinline__ void ffma2(unsigned long long& d,
                                      unsigned long long a, unsigned long long b) {
    asm("fma.rn.f32x2 %0, %1, %2, %0;" : "+l"(d) : "l"(a), "l"(b));
}
__device__ __forceinline__ void unpk2(unsigned long long v, float& lo, float& hi) {
    asm("mov.b64 {%0, %1}, %2;" : "=f"(lo), "=f"(hi) : "l"(v));
}

// ===================== half2 <-> uint bit casts =====================
__device__ __forceinline__ unsigned h2u(__half2 h) {
    return *reinterpret_cast<unsigned*>(&h);
}
__device__ __forceinline__ __half2 u2h(unsigned u) {
    return *reinterpret_cast<__half2*>(&u);
}
__device__ __forceinline__ float2 h22f(unsigned u) {
    return __half22float2(u2h(u));
}

// ===================== device scratch: fp16 pair-interleaved weights =========
// K1 pair p covers m = 2p, 2p+1 at channel c:
//   K1A[p*NC+c] = (m0:(wx0,wx1), m0:(wx2,wy0), m1:(wx0,wx1), m1:(wx2,wy0))  16B
//   K1B[p*NC+c] = (m0:(wy1,wy2), m1:(wy1,wy2))                               8B
// K2 pair p covers cc = 2p, 2p+1:
//   K2A[p*NC+c] = (cc0:(w0,w1), cc0:(w2,w3), cc1:(w0,w1), cc1:(w2,w3))      16B
//   K2B[p*NC+c] = (cc0:(w4,w4), cc1:(w4,w4))                                 8B
__device__ uint4 K1A[(MUL / 2) * NC];
__device__ uint2 K1B[(MUL / 2) * NC];
__device__ uint4 K2A[(NC / 2) * NC];
__device__ uint2 K2B[(NC / 2) * NC];
__device__ float ZS[NBATCH * ZROW];   // 14.7 MB z scratch (padded rows)

__global__ void pack_weights(const float* __restrict__ wx,
                             const float* __restrict__ wy,
                             const float* __restrict__ wz) {
    int idx = blockIdx.x * 256 + threadIdx.x;   // 0..8191 = pair*128 + c
    int pair = idx >> 7;
    int c = idx & 127;
    int i0 = (2 * pair) * NC + c;
    int i1 = (2 * pair + 1) * NC + c;
    {
        unsigned a0 = h2u(__floats2half2_rn(wx[i0], wx[16384 + i0]));          // m0: wx0,wx1
        unsigned b0 = h2u(__floats2half2_rn(wx[32768 + i0], wy[i0]));          // m0: wx2,wy0
        unsigned c0 = h2u(__floats2half2_rn(wy[16384 + i0], wy[32768 + i0]));  // m0: wy1,wy2
        unsigned a1 = h2u(__floats2half2_rn(wx[i1], wx[16384 + i1]));
        unsigned b1 = h2u(__floats2half2_rn(wx[32768 + i1], wy[i1]));
        unsigned c1 = h2u(__floats2half2_rn(wy[16384 + i1], wy[32768 + i1]));
        K1A[idx] = make_uint4(a0, b0, a1, b1);
        K1B[idx] = make_uint2(c0, c1);
    }
    {
        unsigned a0 = h2u(__floats2half2_rn(wz[i0], wz[16384 + i0]));          // cc0: w0,w1
        unsigned b0 = h2u(__floats2half2_rn(wz[32768 + i0], wz[49152 + i0]));  // cc0: w2,w3
        unsigned c0 = h2u(__floats2half2_rn(wz[65536 + i0], wz[65536 + i0]));  // cc0: w4,w4
        unsigned a1 = h2u(__floats2half2_rn(wz[i1], wz[16384 + i1]));
        unsigned b1 = h2u(__floats2half2_rn(wz[32768 + i1], wz[49152 + i1]));
        unsigned c1 = h2u(__floats2half2_rn(wz[65536 + i1], wz[65536 + i1]));
        K2A[idx] = make_uint4(a0, b0, a1, b1);
        K2B[idx] = make_uint2(c0, c1);
    }
}

// ===================== sparse Gaunt contraction (compile-time coeffs) ========
__device__ __forceinline__ void gaunt_contract_ct(const float* __restrict__ xc,
                                                  const float* __restrict__ yc,
                                                  float* __restrict__ z) {
    #pragma unroll
    for (int d = 0; d < DZ; ++d) z[d] = 0.0f;
    sfor<9>([&](auto I) {
        constexpr int i = decltype(I)::value;
        sfor<9>([&](auto J) {
            constexpr int j = decltype(J)::value;
            float p = xc[i] * yc[j];
            sfor<DZ>([&](auto Dd) {
                constexpr int d = decltype(Dd)::value;
                if constexpr (gaunt_nz(i, j, d)) {
                    constexpr float gv = (float)cgaunt::GG.g[i * 9 + j][d];
                    z[d] = fmaf(p, gv, z[d]);
                }
            });
        });
    });
}

// ===================== K1: linear-in + Gaunt -> z scratch =====================
__global__ void __launch_bounds__(128, 9)
k1_linear_gaunt(const float* __restrict__ x, const float* __restrict__ y) {
    __shared__ __align__(16) float pool[ZROW];   // 14336 B

    const int c = threadIdx.x;
    const int n = blockIdx.x;

    // ---- stage-in: xy row m = [xd1..8][yd1..8][xd0][yd0][pad2] ----
    {
        const float* xg = x + (size_t)n * MUL * D1;
        const float* yg = y + (size_t)n * MUL * D1;
        #pragma unroll
        for (int it = 0; it < 9; ++it) {
            int idx = c + it * 128;
            int m = idx / 9, dd = idx - m * 9;
            int kx = (dd == 0) ? 16 : (dd - 1);
            int ky = (dd == 0) ? 17 : (7 + dd);
            pool[m * XYSTRIDE + kx] = xg[idx];
            pool[m * XYSTRIDE + ky] = yg[idx];
        }
    }
    __syncthreads();

    // ---- stage 1: per-l linear in (packed f32x2, pair-interleaved fp16 wts) --
    unsigned long long Ax[4], Ay[4];
    float sx = 0.0f, sy = 0.0f;
    #pragma unroll
    for (int k = 0; k < 4; ++k) { Ax[k] = Ay[k] = 0ULL; }

    #pragma unroll 4
    for (int p = 0; p < MUL / 2; ++p) {
        uint4 wa = K1A[p * NC + c];
        uint2 wb = K1B[p * NC + c];
        // ---- m0 = 2p ----
        {
            float2 t0 = h22f(wa.x);   // wx0, wx1
            float2 t1 = h22f(wa.y);   // wx2, wy0
            float2 t2 = h22f(wb.x);   // wy1, wy2
            const float* row = &pool[(2 * p) * XYSTRIDE];
            float4 xv0 = *(const float4*)(row);
            float4 xv1 = *(const float4*)(row + 4);
            float4 yv0 = *(const float4*)(row + 8);
            float4 yv1 = *(const float4*)(row + 12);
            float2 d0  = *(const float2*)(row + 16);
            ffma2(Ax[0], pk2(xv0.x, xv0.y), pk2(t0.y, t0.y));
            ffma2(Ax[1], pk2(xv0.z, xv0.w), pk2(t0.y, t1.x));
            ffma2(Ax[2], pk2(xv1.x, xv1.y), pk2(t1.x, t1.x));
            ffma2(Ax[3], pk2(xv1.z, xv1.w), pk2(t1.x, t1.x));
            sx += d0.x * t0.x;
            ffma2(Ay[0], pk2(yv0.x, yv0.y), pk2(t2.x, t2.x));
            ffma2(Ay[1], pk2(yv0.z, yv0.w), pk2(t2.x, t2.y));
            ffma2(Ay[2], pk2(yv1.x, yv1.y), pk2(t2.y, t2.y));
            ffma2(Ay[3], pk2(yv1.z, yv1.w), pk2(t2.y, t2.y));
            sy += d0.y * t1.y;
        }
        // ---- m1 = 2p+1 ----
        {
            float2 t0 = h22f(wa.z);
            float2 t1 = h22f(wa.w);
            float2 t2 = h22f(wb.y);
            const float* row = &pool[(2 * p + 1) * XYSTRIDE];
            float4 xv0 = *(const float4*)(row);
            float4 xv1 = *(const float4*)(row + 4);
            float4 yv0 = *(const float4*)(row + 8);
            float4 yv1 = *(const float4*)(row + 12);
            float2 d0  = *(const float2*)(row + 16);
            ffma2(Ax[0], pk2(xv0.x, xv0.y), pk2(t0.y, t0.y));
            ffma2(Ax[1], pk2(xv0.z, xv0.w), pk2(t0.y, t1.x));
            ffma2(Ax[2], pk2(xv1.x, xv1.y), pk2(t1.x, t1.x));
            ffma2(Ax[3], pk2(xv1.z, xv1.w), pk2(t1.x, t1.x));
            sx += d0.x * t0.x;
            ffma2(Ay[0], pk2(yv0.x, yv0.y), pk2(t2.x, t2.x));
            ffma2(Ay[1], pk2(yv0.z, yv0.w), pk2(t2.x, t2.y));
            ffma2(Ay[2], pk2(yv1.x, yv1.y), pk2(t2.y, t2.y));
            ffma2(Ay[3], pk2(yv1.z, yv1.w), pk2(t2.y, t2.y));
            sy += d0.y * t1.y;
        }
    }

    float xc[9], yc[9];
    xc[0] = sx; yc[0] = sy;
    #pragma unroll
    for (int k = 0; k < 4; ++k) {
        unpk2(Ax[k], xc[2 * k + 1], xc[2 * k + 2]);
        unpk2(Ay[k], yc[2 * k + 1], yc[2 * k + 2]);
    }

    // ---- stage 2: sparse Gaunt contraction (registers + immediates only) ----
    float z[DZ];
    gaunt_contract_ct(xc, yc, z);

    __syncthreads();   // all warps done reading xy before z overwrites pool

    // ---- z -> smem padded rows, then coalesced float4 copy to scratch ----
    {
        float* zr = &pool[c * ZSTRIDE];  // 112B stride -> 16B aligned
        *(float4*)(zr)      = make_float4(z[0],  z[1],  z[2],  z[3]);
        *(float4*)(zr + 4)  = make_float4(z[4],  z[5],  z[6],  z[7]);
        *(float4*)(zr + 8)  = make_float4(z[8],  z[9],  z[10], z[11]);
        *(float4*)(zr + 12) = make_float4(z[12], z[13], z[14], z[15]);
        *(float4*)(zr + 16) = make_float4(z[16], z[17], z[18], z[19]);
        *(float4*)(zr + 20) = make_float4(z[20], z[21], z[22], z[23]);
        zr[24] = z[24];
    }
    __syncthreads();

    float4* zg4 = (float4*)(ZS + (size_t)n * ZROW);     // n*14336B, 16B aligned
    const float4* p4 = (const float4*)pool;
    #pragma unroll
    for (int it = 0; it < 7; ++it) {                     // 7*128 = 896 = ZROW/4
        zg4[it * 128 + c] = p4[it * 128 + c];
    }
}

// ===================== K2: channel mixing (pair-interleaved fp16 wts) ========
// d -> l map: d0:w0, d1-3:w1, d4-8:w2, d9-15:w3, d16-24:w4
__global__ void __launch_bounds__(128, 7)
k2_mix(float* __restrict__ out) {
    __shared__ __align__(16) float zs[ZROW];   // 14336 B

    const int c = threadIdx.x;
    const int n = blockIdx.x;

    // ---- stage z in: straight float4 copy (padded layout preserved) ----
    {
        const float4* zg4 = (const float4*)(ZS + (size_t)n * ZROW);
        float4* s4 = (float4*)zs;
        #pragma unroll
        for (int it = 0; it < 7; ++it) {
            s4[it * 128 + c] = zg4[it * 128 + c];
        }
    }
    __syncthreads();

    // ---- per-l channel mixing, packed f32x2, pair-interleaved fp16 wts ----
    unsigned long long a[12];
    float as = 0.0f;
    #pragma unroll
    for (int k = 0; k < 12; ++k) a[k] = 0ULL;

    #pragma unroll 2
    for (int p = 0; p < NC / 2; ++p) {
        uint4 w1 = K2A[p * NC + c];
        uint2 w2 = K2B[p * NC + c];
        #pragma unroll
        for (int s = 0; s < 2; ++s) {
            const int cc = 2 * p + s;
            float2 t0 = h22f(s ? w1.z : w1.x);  // w0, w1
            float2 t1 = h22f(s ? w1.w : w1.y);  // w2, w3
            float2 t2 = h22f(s ? w2.y : w2.x);  // w4, w4
            const float* zp = &zs[cc * ZSTRIDE];
            float4 q0 = *(const float4*)(zp);
            float4 q1 = *(const float4*)(zp + 4);
            float4 q2 = *(const float4*)(zp + 8);
            float4 q3 = *(const float4*)(zp + 12);
            float4 q4 = *(const float4*)(zp + 16);
            float4 q5 = *(const float4*)(zp + 20);
            float  zl = zp[24];
            ffma2(a[0],  pk2(q0.x, q0.y), pk2(t0.x, t0.y));   // d0*w0, d1*w1
            ffma2(a[1],  pk2(q0.z, q0.w), pk2(t0.y, t0.y));   // d2,d3 * w1
            ffma2(a[2],  pk2(q1.x, q1.y), pk2(t1.x, t1.x));   // d4,d5 * w2
            ffma2(a[3],  pk2(q1.z, q1.w), pk2(t1.x, t1.x));   // d6,d7 * w2
            ffma2(a[4],  pk2(q2.x, q2.y), pk2(t1.x, t1.y));   // d8*w2, d9*w3
            ffma2(a[5],  pk2(q2.z, q2.w), pk2(t1.y, t1.y));   // d10,d11 * w3
            ffma2(a[6],  pk2(q3.x, q3.y), pk2(t1.y, t1.y));   // d12,d13 * w3
            ffma2(a[7],  pk2(q3.z, q3.w), pk2(t1.y, t1.y));   // d14,d15 * w3
            ffma2(a[8],  pk2(q4.x, q4.y), pk2(t2.x, t2.x));   // d16,d17 * w4
            ffma2(a[9],  pk2(q4.z, q4.w), pk2(t2.x, t2.x));   // d18,d19 * w4
            ffma2(a[10], pk2(q5.x, q5.y), pk2(t2.x, t2.x));   // d20,d21 * w4
            ffma2(a[11], pk2(q5.z, q5.w), pk2(t2.x, t2.x));   // d22,d23 * w4
            as += zl * t2.x;                                   // d24*w4
        }
    }
    __syncthreads();   // everyone done reading zs before epilogue overwrites it

    // ---- epilogue: accums -> smem unpadded (stride 25: conflict-free), ----
    // ---- then fully coalesced copy to out                               ----
    {
        float* r = &zs[c * DZ];
        #pragma unroll
        for (int k = 0; k < 12; ++k) {
            float lo, hi;
            unpk2(a[k], lo, hi);
            r[2 * k] = lo;
            r[2 * k + 1] = hi;
        }
        r[24] = as;
    }
    __syncthreads();

    float* og = out + (size_t)n * (NC * DZ);            // n*12800B: 16B aligned
    float4* og4 = (float4*)og;
    const float4* s4 = (const float4*)zs;
    #pragma unroll
    for (int it = 0; it < 6; ++it) {                     // 6*128*4 = 3072 floats
        og4[it * 128 + c] = s4[it * 128 + c];
    }
    og[3072 + c] = zs[3072 + c];                         // tail 128 floats
}

extern "C" void kernel_launch(void* const* d_in, const int* in_sizes, int n_in,
                              void* d_out, int out_size) {
    const float* x  = (const float*)d_in[0];
    const float* y  = (const float*)d_in[1];
    const float* wx = (const float*)d_in[2];
    const float* wy = (const float*)d_in[3];
    const float* wz = (const float*)d_in[4];
    float* out = (float*)d_out;

    pack_weights<<<32, 256>>>(wx, wy, wz);
    k1_linear_gaunt<<<NBATCH, 128>>>(x, y);
    k2_mix<<<NBATCH, 128>>>(out);
}